// round 16
// baseline (speedup 1.0000x reference)
#include <cuda_runtime.h>
#include <cuda_fp16.h>
#include <cstdint>

#define TPB 512

// smem byte offsets
#define OF_WC 0u             // 32KB fp16 Wcf (128 rows x 256B, swizzled)
#define OF_WF 32768u         // 32KB fp16 Wfc
#define OF_WD 65536u         // 8KB fp16 Wdf (hoisted to regs at init)
#define SLICEQ(q) (73728u + (uint32_t)(q) * 28672u)  // per-quad slice, 4 quads
//   +0     : fp16 src buf0 32x128 (8KB)
//   +8192  : fp16 src buf1 (8KB)
//   +16384 : fp16 he buf0 32x32 (2KB)
//   +18432 : fp16 he buf1 (2KB)
//   +20480 : fp16 h 32x128 (8KB)
#define OF_BC 188416u
#define OF_BD 188928u
#define OF_BF 189440u
#define SMEM_BYTES 189952u

__device__ __forceinline__ void ldsm4(uint32_t r[4], uint32_t a) {
    asm volatile("ldmatrix.sync.aligned.m8n8.x4.shared.b16 {%0,%1,%2,%3}, [%4];"
                 : "=r"(r[0]), "=r"(r[1]), "=r"(r[2]), "=r"(r[3]) : "r"(a));
}

__device__ __forceinline__ void stsm4(uint32_t a, uint32_t r0, uint32_t r1,
                                      uint32_t r2, uint32_t r3) {
    asm volatile("stmatrix.sync.aligned.m8n8.x4.shared.b16 [%0], {%1,%2,%3,%4};"
                 :: "r"(a), "r"(r0), "r"(r1), "r"(r2), "r"(r3) : "memory");
}

__device__ __forceinline__ void sts64(uint32_t a, uint32_t lo, uint32_t hi) {
    asm volatile("st.shared.v2.b32 [%0], {%1,%2};"
                 :: "r"(a), "r"(lo), "r"(hi) : "memory");
}

__device__ __forceinline__ void mma16(float* c, const uint32_t* a, uint32_t b0, uint32_t b1) {
    asm volatile(
        "mma.sync.aligned.m16n8k16.row.col.f32.f16.f16.f32 "
        "{%0,%1,%2,%3}, {%4,%5,%6,%7}, {%8,%9}, {%0,%1,%2,%3};\n"
        : "+f"(c[0]), "+f"(c[1]), "+f"(c[2]), "+f"(c[3])
        : "r"(a[0]), "r"(a[1]), "r"(a[2]), "r"(a[3]), "r"(b0), "r"(b1));
}

// f16-accumulator mma — GEMM2 only (K=32, bias preloaded into acc)
__device__ __forceinline__ void mma16h(uint32_t* c, const uint32_t* a, uint32_t b0, uint32_t b1) {
    asm volatile(
        "mma.sync.aligned.m16n8k16.row.col.f16.f16.f16.f16 "
        "{%0,%1}, {%2,%3,%4,%5}, {%6,%7}, {%0,%1};\n"
        : "+r"(c[0]), "+r"(c[1])
        : "r"(a[0]), "r"(a[1]), "r"(a[2]), "r"(a[3]), "r"(b0), "r"(b1));
}

__device__ __forceinline__ float ftanh(float x) {
    float r;
    asm("tanh.approx.f32 %0, %1;" : "=f"(r) : "f"(x));
    return r;
}

__device__ __forceinline__ uint32_t pack2(float a, float b) {
    __half2 h = __floats2half2_rn(a, b);
    return *(uint32_t*)&h;
}
__device__ __forceinline__ float2 unp2(uint32_t u) {
    __half2 h = *(__half2*)&u;
    return __half22float2(h);
}

__device__ __forceinline__ void qbar(int quad) {
    asm volatile("bar.sync %0, 128;" :: "r"(quad + 1) : "memory");
}

__device__ __forceinline__ uint32_t a16(uint32_t row, uint32_t ch) {
    return row * 256u + ((ch ^ (row & 7u)) << 4);
}
__device__ __forceinline__ uint32_t h16(uint32_t row, uint32_t ch) {
    return row * 64u + ((ch ^ ((row >> 1) & 3u)) << 4);
}

// STS of one converted src chunk (16B fp32 in regs -> 8B fp16, swizzled)
__device__ __forceinline__ void sts_src(uint32_t base, int i, float4 u) {
    uint32_t row = (uint32_t)(i >> 5);
    uint32_t c8  = (uint32_t)(i & 31);
    uint32_t off = row * 256u + (((c8 >> 1) ^ (row & 7u)) << 4) + (c8 & 1u) * 8u;
    sts64(base + off, pack2(u.x, u.y), pack2(u.z, u.w));
}
__device__ __forceinline__ void sts_he(uint32_t base, int i, float4 u) {
    uint32_t row = (uint32_t)(i >> 3);
    uint32_t c8  = (uint32_t)(i & 7);
    uint32_t off = row * 64u + (((c8 >> 1) ^ ((row >> 1) & 3u)) << 4) + (c8 & 1u) * 8u;
    sts64(base + off, pack2(u.x, u.y), pack2(u.z, u.w));
}

__global__ void __launch_bounds__(TPB, 1)
dtnn_kernel(const float* __restrict__ gsrc, const float* __restrict__ ghe,
            const float* __restrict__ Wcf,  const float* __restrict__ bcf,
            const float* __restrict__ Wdf,  const float* __restrict__ bdf,
            const float* __restrict__ Wfc,  const float* __restrict__ bfc,
            float* __restrict__ out, int ntiles)
{
    extern __shared__ __align__(1024) unsigned char sm[];
    uint32_t smb;
    asm("{.reg .u64 t; cvta.to.shared.u64 t, %1; cvt.u32.u64 %0, t;}"
        : "=r"(smb) : "l"(sm));

    float* bC = (float*)(sm + OF_BC);
    float* bD = (float*)(sm + OF_BD);
    float* bF = (float*)(sm + OF_BF);

    const int tid  = threadIdx.x;
    const int lane = tid & 31;
    const int wid  = tid >> 5;
    const int tg   = lane & 3;
    const int quad = wid >> 2;            // node within tile; owns rows [32q, 32q+32)
    const int qtid = tid & 127;
    const int n0   = (wid & 3) * 32;      // column quarter
    const int grid = gridDim.x;

    // ---- one-time weight + bias staging ----
    for (int i = tid; i < 2048; i += TPB) {
        int row = i >> 4, ch = i & 15;
        float4 u = ((const float4*)Wcf)[row * 32 + ch * 2];
        float4 v = ((const float4*)Wcf)[row * 32 + ch * 2 + 1];
        uint4 w = {pack2(u.x, u.y), pack2(u.z, u.w), pack2(v.x, v.y), pack2(v.z, v.w)};
        *(uint4*)(sm + OF_WC + a16(row, ch)) = w;
        u = ((const float4*)Wfc)[row * 32 + ch * 2];
        v = ((const float4*)Wfc)[row * 32 + ch * 2 + 1];
        uint4 w2 = {pack2(u.x, u.y), pack2(u.z, u.w), pack2(v.x, v.y), pack2(v.z, v.w)};
        *(uint4*)(sm + OF_WF + a16(row, ch)) = w2;
    }
    for (int i = tid; i < 512; i += TPB) {
        int row = i >> 2, ch = i & 3;
        float4 u = ((const float4*)Wdf)[row * 8 + ch * 2];
        float4 v = ((const float4*)Wdf)[row * 8 + ch * 2 + 1];
        uint4 w = {pack2(u.x, u.y), pack2(u.z, u.w), pack2(v.x, v.y), pack2(v.z, v.w)};
        *(uint4*)(sm + OF_WD + h16(row, ch)) = w;
    }
    if (tid < 128) { bC[tid] = bcf[tid]; bD[tid] = bdf[tid]; bF[tid] = bfc[tid]; }
    __syncthreads();

    // ---- per-lane ldmatrix constants ----
    const uint32_t mrow = (uint32_t)((lane & 7) | (((lane >> 3) & 1) << 3));
    const uint32_t ksel = (uint32_t)((lane >> 4) & 1);
    const uint32_t key8 = mrow & 7u;
    const uint32_t keyh = (mrow >> 1) & 3u;

    const uint32_t slice = smb + SLICEQ(quad);
    const uint32_t hBa   = slice + 20480u + mrow * 256u;   // h A base
    const uint32_t hBst  = slice + 20480u;                 // h store base
    const uint32_t wc0 = smb + OF_WC + ((uint32_t)n0 + mrow) * 256u;
    const uint32_t wf0 = smb + OF_WF + ((uint32_t)n0 + mrow) * 256u;
    uint32_t wdr[2][2][4];   // hoisted Wdf fragments [kt][p][4]
    {
        uint32_t wdB[2];
        #pragma unroll
        for (int p = 0; p < 2; p++)
            wdB[p] = smb + OF_WD + ((uint32_t)(n0 + 16 * p) + mrow) * 64u;
        #pragma unroll
        for (int kt = 0; kt < 2; kt++) {
            uint32_t ub = ((2u * kt + ksel) ^ keyh) << 4;
            ldsm4(wdr[kt][0], wdB[0] + ub);
            ldsm4(wdr[kt][1], wdB[1] + ub);
        }
    }
    const uint32_t srow = (uint32_t)(((lane >> 4) & 1) * 16 + ((lane >> 3) & 1) * 8
                                     + (lane & 7));
    __syncthreads();   // Wdf reads complete before any buffer writes alias nothing (safety)

    // ---- prologue: fill buffers[0] for tile0 via direct LDG + convert ----
    {
        const float4* sp = (const float4*)(gsrc + (size_t)blockIdx.x * 16384 + quad * 4096);
        const float4* hp = (const float4*)(ghe + (size_t)blockIdx.x * 4096 + quad * 1024);
        float4 sv[8], hv[2];
        #pragma unroll
        for (int jt = 0; jt < 8; jt++) sv[jt] = sp[qtid + jt * 128];
        hv[0] = hp[qtid];
        hv[1] = hp[qtid + 128];
        #pragma unroll
        for (int jt = 0; jt < 8; jt++) sts_src(slice, qtid + jt * 128, sv[jt]);
        sts_he(slice + 16384u, qtid, hv[0]);
        sts_he(slice + 16384u, qtid + 128, hv[1]);
    }
    qbar(quad);

    int cur = 0;
    for (int tile = blockIdx.x; tile < ntiles; tile += grid, cur ^= 1) {
        const uint32_t srcB = slice + (uint32_t)cur * 8192u + mrow * 256u;
        const uint32_t heB  = slice + 16384u + (uint32_t)cur * 2048u + mrow * 64u;
        const bool have_next = (tile + grid < ntiles);
        const float4* spN = (const float4*)(gsrc + (size_t)(tile + grid) * 16384
                                            + quad * 4096);
        const float4* hpN = (const float4*)(ghe + (size_t)(tile + grid) * 4096
                                            + quad * 1024);

        // 1. GEMM2 (f16 acc, bias preloaded)
        uint32_t accEp[2][4][2];
        #pragma unroll
        for (int nt = 0; nt < 4; nt++) {
            int c = n0 + nt * 8 + 2 * tg;
            float2 bd2 = *(float2*)(bD + c);
            uint32_t bini = pack2(bd2.x, bd2.y);
            accEp[0][nt][0] = bini; accEp[0][nt][1] = bini;
            accEp[1][nt][0] = bini; accEp[1][nt][1] = bini;
        }
        #pragma unroll
        for (int kt = 0; kt < 2; kt++) {
            uint32_t ua = ((2u * kt + ksel) ^ keyh) << 4;
            uint32_t A0[4], A1[4];
            ldsm4(A0, heB + ua);
            ldsm4(A1, heB + 1024u + ua);
            #pragma unroll
            for (int p = 0; p < 2; p++) {
                mma16h(accEp[0][2 * p],     A0, wdr[kt][p][0], wdr[kt][p][2]);
                mma16h(accEp[0][2 * p + 1], A0, wdr[kt][p][1], wdr[kt][p][3]);
                mma16h(accEp[1][2 * p],     A1, wdr[kt][p][0], wdr[kt][p][2]);
                mma16h(accEp[1][2 * p + 1], A1, wdr[kt][p][1], wdr[kt][p][3]);
            }
        }

        // 2. GEMM1
        float accC[2][4][4];
        #pragma unroll
        for (int mt = 0; mt < 2; mt++)
            #pragma unroll
            for (int nt = 0; nt < 4; nt++)
                accC[mt][nt][0] = accC[mt][nt][1] = accC[mt][nt][2] = accC[mt][nt][3] = 0.f;
        #pragma unroll
        for (int kt = 0; kt < 8; kt++) {
            uint32_t ua = ((2u * kt + ksel) ^ key8) << 4;
            uint32_t A0[4], A1[4], B0[4], B1[4];
            ldsm4(A0, srcB + ua);
            ldsm4(A1, srcB + 4096u + ua);
            ldsm4(B0, wc0 + ua);
            ldsm4(B1, wc0 + 4096u + ua);
            mma16(accC[0][0], A0, B0[0], B0[2]);
            mma16(accC[0][1], A0, B0[1], B0[3]);
            mma16(accC[0][2], A0, B1[0], B1[2]);
            mma16(accC[0][3], A0, B1[1], B1[3]);
            mma16(accC[1][0], A1, B0[0], B0[2]);
            mma16(accC[1][1], A1, B0[1], B0[3]);
            mma16(accC[1][2], A1, B1[0], B1[2]);
            mma16(accC[1][3], A1, B1[1], B1[3]);
        }

        // 3. gate -> h buffer (accEp dies here)
        #pragma unroll
        for (int nt = 0; nt < 4; nt++) {
            int c = n0 + nt * 8 + 2 * tg;
            float2 bc2 = *(float2*)(bC + c);
            float2 e00 = unp2(accEp[0][nt][0]);
            float2 e01 = unp2(accEp[0][nt][1]);
            float2 e10 = unp2(accEp[1][nt][0]);
            float2 e11 = unp2(accEp[1][nt][1]);
            uint32_t p0 = pack2((accC[0][nt][0] + bc2.x) * e00.x,
                                (accC[0][nt][1] + bc2.y) * e00.y);
            uint32_t p1 = pack2((accC[0][nt][2] + bc2.x) * e01.x,
                                (accC[0][nt][3] + bc2.y) * e01.y);
            uint32_t p2 = pack2((accC[1][nt][0] + bc2.x) * e10.x,
                                (accC[1][nt][1] + bc2.y) * e10.y);
            uint32_t p3 = pack2((accC[1][nt][2] + bc2.x) * e11.x,
                                (accC[1][nt][3] + bc2.y) * e11.y);
            uint32_t ch = (uint32_t)(n0 >> 3) + (uint32_t)nt;
            stsm4(hBst + a16(srow, ch), p0, p1, p2, p3);
        }
        qbar(quad);    // h visible; all quad warps past GEMM1/GEMM2 reads of buffers[cur]

        // 4. LDG batch1 for next tile (16 regs; latency covered by GEMM3)
        float4 sv0, sv1, sv2, sv3;
        if (have_next) {
            sv0 = spN[qtid];
            sv1 = spN[qtid + 128];
            sv2 = spN[qtid + 256];
            sv3 = spN[qtid + 384];
        }

        // 5. GEMM3 (reuse accC)
        #pragma unroll
        for (int mt = 0; mt < 2; mt++)
            #pragma unroll
            for (int nt = 0; nt < 4; nt++)
                accC[mt][nt][0] = accC[mt][nt][1] = accC[mt][nt][2] = accC[mt][nt][3] = 0.f;
        #pragma unroll
        for (int kt = 0; kt < 8; kt++) {
            uint32_t ua = ((2u * kt + ksel) ^ key8) << 4;
            uint32_t A0[4], A1[4], B0[4], B1[4];
            ldsm4(A0, hBa + ua);
            ldsm4(A1, hBa + 4096u + ua);
            ldsm4(B0, wf0 + ua);
            ldsm4(B1, wf0 + 4096u + ua);
            mma16(accC[0][0], A0, B0[0], B0[2]);
            mma16(accC[0][1], A0, B0[1], B0[3]);
            mma16(accC[0][2], A0, B1[0], B1[2]);
            mma16(accC[0][3], A0, B1[1], B1[3]);
            mma16(accC[1][0], A1, B0[0], B0[2]);
            mma16(accC[1][1], A1, B0[1], B0[3]);
            mma16(accC[1][2], A1, B1[0], B1[2]);
            mma16(accC[1][3], A1, B1[1], B1[3]);
        }

        // 6. STS batch1 into buffers[cur^1]; issue LDG batch2 + he (24 regs,
        //    latency covered by the epilogue below)
        const uint32_t nslice = slice + (uint32_t)(cur ^ 1) * 8192u;
        const uint32_t nhe    = slice + 16384u + (uint32_t)(cur ^ 1) * 2048u;
        float4 sv4, sv5, sv6, sv7, hv0, hv1;
        if (have_next) {
            sts_src(nslice, qtid,       sv0);
            sts_src(nslice, qtid + 128, sv1);
            sts_src(nslice, qtid + 256, sv2);
            sts_src(nslice, qtid + 384, sv3);
            sv4 = spN[qtid + 512];
            sv5 = spN[qtid + 640];
            sv6 = spN[qtid + 768];
            sv7 = spN[qtid + 896];
            hv0 = hpN[qtid];
            hv1 = hpN[qtid + 128];
        }

        // 7. epilogue: tanh + mailbox reduce (covers batch2 LDG latency)
        {
            const int node = tile * 4 + quad;
            float v[8];
            #pragma unroll
            for (int nt = 0; nt < 4; nt++) {
                int c = n0 + nt * 8 + 2 * tg;
                float2 bf2 = *(float2*)(bF + c);
                v[2 * nt]     = ftanh(accC[0][nt][0] + bf2.x) + ftanh(accC[0][nt][2] + bf2.x)
                              + ftanh(accC[1][nt][0] + bf2.x) + ftanh(accC[1][nt][2] + bf2.x);
                v[2 * nt + 1] = ftanh(accC[0][nt][1] + bf2.y) + ftanh(accC[0][nt][3] + bf2.y)
                              + ftanh(accC[1][nt][1] + bf2.y) + ftanh(accC[1][nt][3] + bf2.y);
            }
            #pragma unroll
            for (int m = 4; m < 32; m <<= 1) {
                #pragma unroll
                for (int i = 0; i < 8; i++)
                    v[i] += __shfl_xor_sync(0xffffffffu, v[i], m);
            }
            if (lane < 4) {
                #pragma unroll
                for (int nt = 0; nt < 4; nt++) {
                    float2 o = {v[2 * nt], v[2 * nt + 1]};
                    *(float2*)(out + (size_t)node * 128 + n0 + nt * 8 + 2 * tg) = o;
                }
            }
        }

        // 8. STS batch2 + he into buffers[cur^1]
        if (have_next) {
            sts_src(nslice, qtid + 512, sv4);
            sts_src(nslice, qtid + 640, sv5);
            sts_src(nslice, qtid + 768, sv6);
            sts_src(nslice, qtid + 896, sv7);
            sts_he(nhe, qtid,       hv0);
            sts_he(nhe, qtid + 128, hv1);
        }
        qbar(quad);    // buffers[cur^1] fully visible before next iteration's GEMMs
    }
}

extern "C" void kernel_launch(void* const* d_in, const int* in_sizes, int n_in,
                              void* d_out, int out_size)
{
    const float* src = (const float*)d_in[0];
    const float* he  = (const float*)d_in[1];
    const float* Wcf = (const float*)d_in[2];
    const float* bcf = (const float*)d_in[3];
    const float* Wdf = (const float*)d_in[4];
    const float* bdf = (const float*)d_in[5];
    const float* Wfc = (const float*)d_in[6];
    const float* bfc = (const float*)d_in[7];
    float* out = (float*)d_out;

    int ntiles = in_sizes[0] / 16384;   // 128 pairs (4 nodes) per tile

    int nsm = 148;
    cudaDeviceGetAttribute(&nsm, cudaDevAttrMultiProcessorCount, 0);
    int grid = nsm < ntiles ? nsm : ntiles;

    cudaFuncSetAttribute(dtnn_kernel, cudaFuncAttributeMaxDynamicSharedMemorySize,
                         (int)SMEM_BYTES);
    dtnn_kernel<<<grid, TPB, SMEM_BYTES>>>(src, he, Wcf, bcf, Wdf, bdf, Wfc, bfc,
                                           out, ntiles);
}